// round 1
// baseline (speedup 1.0000x reference)
#include <cuda_runtime.h>

// ---------------------------------------------------------------------------
// GAT (4 layers) + pairwise tanh output for GB300.
// Pipeline per launch:
//   1. deterministic CSR build (chunked stable counting sort by dst)
//   2. per layer: SGEMM (f = h @ W) -> el/er attention dots -> warp-per-node
//      edge-softmax aggregation (+bias, elu)  [layer 3: head-mean -> s1/s2]
//   3. pairwise: OD[i,j] = tanh(s2[i] + s1[j] + dis[i,j]*pw[128] + pb)
// ---------------------------------------------------------------------------

constexpr int HD  = 384;        // H*D
constexpr int NH  = 6;          // heads
constexpr int NQ  = HD / 4;     // float4 per feature row (96)
constexpr int NMAXI = 5120;     // max nodes (actual 5000)
constexpr int EMAXI = 163840;   // max edges (actual 160000)
constexpr int CSZ   = 320;      // edges per sort chunk
constexpr int NCH   = 512;      // max chunks (actual 500)

// ------------------------- device scratch (static) -------------------------
__device__ __align__(16) float g_f[NMAXI * HD];   // GEMM output (current layer f)
__device__ __align__(16) float g_h[NMAXI * HD];   // layer output / next input
__device__ float g_el[NMAXI * NH];
__device__ float g_er[NMAXI * NH];
__device__ int   g_hist[NCH * NMAXI];             // per-chunk per-node counts/offsets
__device__ int   g_base[NMAXI];                   // CSR row base
__device__ int   g_deg[NMAXI];                    // in-degree per node
__device__ int   g_csr[EMAXI];                    // src node per sorted edge slot
__device__ __align__(16) float g_s1[NMAXI];
__device__ __align__(16) float g_s2[NMAXI];

// ----------------------------- CSR build -----------------------------------
__global__ void k_hist(const int* __restrict__ dst, int E, int N) {
    int c = blockIdx.x;
    int* row = g_hist + c * N;
    for (int i = threadIdx.x; i < N; i += blockDim.x) row[i] = 0;
    __syncthreads();
    int e0 = c * CSZ;
    for (int i = threadIdx.x; i < CSZ; i += blockDim.x) {
        int e = e0 + i;
        if (e < E) atomicAdd(&row[dst[e]], 1);
    }
}

// per node: exclusive scan across chunks; g_hist[c][n] becomes chunk-local
// base offset, g_deg[n] = total in-degree.
__global__ void k_cscan(int N, int nchunk) {
    int w    = (blockIdx.x * blockDim.x + threadIdx.x) >> 5;
    int lane = threadIdx.x & 31;
    if (w >= N) return;
    int running = 0;
    for (int cb = 0; cb < nchunk; cb += 32) {
        int c = cb + lane;
        int v = (c < nchunk) ? g_hist[c * N + w] : 0;
        int s = v;
        #pragma unroll
        for (int o = 1; o < 32; o <<= 1) {
            int t = __shfl_up_sync(0xffffffffu, s, o);
            if (lane >= o) s += t;
        }
        if (c < nchunk) g_hist[c * N + w] = running + (s - v);
        running += __shfl_sync(0xffffffffu, s, 31);
    }
    if (lane == 0) g_deg[w] = running;
}

// single-block exclusive scan of g_deg -> g_base  (N <= 8192)
__global__ void k_scan(int N) {
    __shared__ int wsum[32];
    int tid = threadIdx.x;
    int CH = (N + 1023) >> 10;   // elements per thread (<=8)
    int start = tid * CH;
    int loc[8];
    int sum = 0;
    #pragma unroll
    for (int i = 0; i < 8; ++i) {
        if (i < CH) {
            int idx = start + i;
            int v = (idx < N) ? g_deg[idx] : 0;
            loc[i] = sum;
            sum += v;
        }
    }
    int lane = tid & 31, wid = tid >> 5;
    int s = sum;
    #pragma unroll
    for (int o = 1; o < 32; o <<= 1) {
        int t = __shfl_up_sync(0xffffffffu, s, o);
        if (lane >= o) s += t;
    }
    if (lane == 31) wsum[wid] = s;
    __syncthreads();
    if (wid == 0) {
        int v = wsum[lane];
        #pragma unroll
        for (int o = 1; o < 32; o <<= 1) {
            int t = __shfl_up_sync(0xffffffffu, v, o);
            if (lane >= o) v += t;
        }
        wsum[lane] = v;
    }
    __syncthreads();
    int tbase = s - sum + (wid > 0 ? wsum[wid - 1] : 0);
    #pragma unroll
    for (int i = 0; i < 8; ++i) {
        if (i < CH) {
            int idx = start + i;
            if (idx < N) g_base[idx] = tbase + loc[i];
        }
    }
}

// stable scatter: within each chunk a single thread walks edges in index
// order, so the final CSR order is exactly edge-index order per dst.
__global__ void k_scatter(const int* __restrict__ src, const int* __restrict__ dst,
                          int E, int N) {
    __shared__ int cur[NMAXI];
    __shared__ int sd[CSZ], ss[CSZ];
    int c = blockIdx.x;
    for (int i = threadIdx.x; i < N; i += blockDim.x)
        cur[i] = g_base[i] + g_hist[c * N + i];
    int e0 = c * CSZ;
    for (int i = threadIdx.x; i < CSZ; i += blockDim.x) {
        int e = e0 + i;
        sd[i] = (e < E) ? dst[e] : -1;
        ss[i] = (e < E) ? src[e] : 0;
    }
    __syncthreads();
    if (threadIdx.x == 0) {
        for (int i = 0; i < CSZ; ++i) {
            int d = sd[i];
            if (d >= 0) {
                int p = cur[d]++;
                g_csr[p] = ss[i];
            }
        }
    }
}

// ------------------------------ SGEMM --------------------------------------
// C(g_f)[M, 384] = A[M, K] @ B[K, 384]; 128x64 tile, 256 threads, 8x4/thread
__global__ __launch_bounds__(256) void k_gemm(const float* __restrict__ Ain,
                                              const float* __restrict__ B,
                                              int M, int K) {
    const float* A = Ain ? Ain : g_h;
    __shared__ float As[16][132];   // +4 pad (transposed A tile)
    __shared__ float Bs[16][64];
    int tid = threadIdx.x;
    int tx = tid & 15, ty = tid >> 4;
    int m0 = blockIdx.y * 128;
    int n0 = blockIdx.x * 64;
    float acc[8][4];
    #pragma unroll
    for (int i = 0; i < 8; ++i)
        #pragma unroll
        for (int j = 0; j < 4; ++j) acc[i][j] = 0.f;

    for (int k0 = 0; k0 < K; k0 += 16) {
        #pragma unroll
        for (int i = 0; i < 8; ++i) {
            int idx = i * 256 + tid;
            int r = idx >> 4, cc = idx & 15;
            int gm = m0 + r, gk = k0 + cc;
            As[cc][r] = (gm < M && gk < K) ? A[(long)gm * K + gk] : 0.f;
        }
        #pragma unroll
        for (int i = 0; i < 4; ++i) {
            int idx = i * 256 + tid;
            int r = idx >> 6, cc = idx & 63;
            int gk = k0 + r;
            Bs[r][cc] = (gk < K) ? B[(long)gk * HD + n0 + cc] : 0.f;
        }
        __syncthreads();
        #pragma unroll
        for (int kk = 0; kk < 16; ++kk) {
            float4 ra0 = *reinterpret_cast<const float4*>(&As[kk][ty * 8]);
            float4 ra1 = *reinterpret_cast<const float4*>(&As[kk][ty * 8 + 4]);
            float4 rb  = *reinterpret_cast<const float4*>(&Bs[kk][tx * 4]);
            float ra[8] = {ra0.x, ra0.y, ra0.z, ra0.w, ra1.x, ra1.y, ra1.z, ra1.w};
            float rv[4] = {rb.x, rb.y, rb.z, rb.w};
            #pragma unroll
            for (int i = 0; i < 8; ++i)
                #pragma unroll
                for (int j = 0; j < 4; ++j)
                    acc[i][j] = fmaf(ra[i], rv[j], acc[i][j]);
        }
        __syncthreads();
    }
    #pragma unroll
    for (int i = 0; i < 8; ++i) {
        int gm = m0 + ty * 8 + i;
        if (gm < M) {
            float4 v = {acc[i][0], acc[i][1], acc[i][2], acc[i][3]};
            *reinterpret_cast<float4*>(&g_f[(long)gm * HD + n0 + tx * 4]) = v;
        }
    }
}

// ----------------------- per-node attention dots ---------------------------
__global__ void k_attn(const float* __restrict__ al, const float* __restrict__ ar,
                       int N) {
    int w    = (blockIdx.x * blockDim.x + threadIdx.x) >> 5;
    int lane = threadIdx.x & 31;
    if (w >= N) return;
    const float* fr = g_f + (long)w * HD;
    #pragma unroll
    for (int h = 0; h < NH; ++h) {
        float a = fr[h * 64 + lane];
        float b = fr[h * 64 + 32 + lane];
        float sl = a * al[h * 64 + lane] + b * al[h * 64 + 32 + lane];
        float sr = a * ar[h * 64 + lane] + b * ar[h * 64 + 32 + lane];
        #pragma unroll
        for (int o = 16; o; o >>= 1) {
            sl += __shfl_xor_sync(0xffffffffu, sl, o);
            sr += __shfl_xor_sync(0xffffffffu, sr, o);
        }
        if (lane == 0) { g_el[w * NH + h] = sl; g_er[w * NH + h] = sr; }
    }
}

// ------------------- edge softmax + aggregation (warp/node) ----------------
// lane j accumulates float4 slots q = j + 32*k4 (k4=0..2); head(q) = (j>>4)+2*k4.
template <bool FINAL>
__global__ void k_agg(const float* __restrict__ bias, const float* __restrict__ pw,
                      int N) {
    int w    = (blockIdx.x * blockDim.x + threadIdx.x) >> 5;
    int lane = threadIdx.x & 31;
    if (w >= N) return;
    float er_l = (lane < NH) ? g_er[w * NH + lane] : 0.f;
    int b0 = g_base[w], dg = g_deg[w];
    float4 a0 = {0.f, 0.f, 0.f, 0.f}, a1 = a0, a2 = a0;
    float den_l = 0.f;
    int h0 = lane >> 4;
    const float4* f4 = reinterpret_cast<const float4*>(g_f);

    for (int p = 0; p < dg; ++p) {
        int s = g_csr[b0 + p];
        float w_l = 0.f;
        if (lane < NH) {
            float e = g_el[s * NH + lane] + er_l;
            e = e > 0.f ? e : 0.2f * e;          // leaky_relu(., 0.2)
            w_l = __expf(e);                     // no max-sub needed (|e| small)
            den_l += w_l;
        }
        float w0 = __shfl_sync(0xffffffffu, w_l, h0);
        float w1 = __shfl_sync(0xffffffffu, w_l, h0 + 2);
        float w2 = __shfl_sync(0xffffffffu, w_l, h0 + 4);
        const float4* fr = f4 + (long)s * NQ;
        float4 v0 = fr[lane], v1 = fr[lane + 32], v2 = fr[lane + 64];
        a0.x = fmaf(w0, v0.x, a0.x); a0.y = fmaf(w0, v0.y, a0.y);
        a0.z = fmaf(w0, v0.z, a0.z); a0.w = fmaf(w0, v0.w, a0.w);
        a1.x = fmaf(w1, v1.x, a1.x); a1.y = fmaf(w1, v1.y, a1.y);
        a1.z = fmaf(w1, v1.z, a1.z); a1.w = fmaf(w1, v1.w, a1.w);
        a2.x = fmaf(w2, v2.x, a2.x); a2.y = fmaf(w2, v2.y, a2.y);
        a2.z = fmaf(w2, v2.z, a2.z); a2.w = fmaf(w2, v2.w, a2.w);
    }

    float d0 = __shfl_sync(0xffffffffu, den_l, h0);
    float d1 = __shfl_sync(0xffffffffu, den_l, h0 + 2);
    float d2 = __shfl_sync(0xffffffffu, den_l, h0 + 4);
    float i0 = (dg > 0) ? 1.f / d0 : 0.f;
    float i1 = (dg > 0) ? 1.f / d1 : 0.f;
    float i2 = (dg > 0) ? 1.f / d2 : 0.f;
    const float4* b4 = reinterpret_cast<const float4*>(bias);
    float4 bv0 = b4[lane], bv1 = b4[lane + 32], bv2 = b4[lane + 64];
    float4 r0, r1, r2;
    r0.x = a0.x * i0 + bv0.x; r0.y = a0.y * i0 + bv0.y;
    r0.z = a0.z * i0 + bv0.z; r0.w = a0.w * i0 + bv0.w;
    r1.x = a1.x * i1 + bv1.x; r1.y = a1.y * i1 + bv1.y;
    r1.z = a1.z * i1 + bv1.z; r1.w = a1.w * i1 + bv1.w;
    r2.x = a2.x * i2 + bv2.x; r2.y = a2.y * i2 + bv2.y;
    r2.z = a2.z * i2 + bv2.z; r2.w = a2.w * i2 + bv2.w;

    if (!FINAL) {
        // elu
        r0.x = r0.x > 0.f ? r0.x : expm1f(r0.x);
        r0.y = r0.y > 0.f ? r0.y : expm1f(r0.y);
        r0.z = r0.z > 0.f ? r0.z : expm1f(r0.z);
        r0.w = r0.w > 0.f ? r0.w : expm1f(r0.w);
        r1.x = r1.x > 0.f ? r1.x : expm1f(r1.x);
        r1.y = r1.y > 0.f ? r1.y : expm1f(r1.y);
        r1.z = r1.z > 0.f ? r1.z : expm1f(r1.z);
        r1.w = r1.w > 0.f ? r1.w : expm1f(r1.w);
        r2.x = r2.x > 0.f ? r2.x : expm1f(r2.x);
        r2.y = r2.y > 0.f ? r2.y : expm1f(r2.y);
        r2.z = r2.z > 0.f ? r2.z : expm1f(r2.z);
        r2.w = r2.w > 0.f ? r2.w : expm1f(r2.w);
        float4* o4 = reinterpret_cast<float4*>(g_h) + (long)w * NQ;
        o4[lane] = r0; o4[lane + 32] = r1; o4[lane + 64] = r2;
    } else {
        // head-mean -> emb; fold immediately into s1 = emb.pw[0:64], s2 = emb.pw[64:128]
        float pt0 = r0.x + r1.x + r2.x;
        float pt1 = r0.y + r1.y + r2.y;
        float pt2 = r0.z + r1.z + r2.z;
        float pt3 = r0.w + r1.w + r2.w;
        int dbase = (4 * lane) & 63;
        float c1 = pt0 * pw[dbase]     + pt1 * pw[dbase + 1]
                 + pt2 * pw[dbase + 2] + pt3 * pw[dbase + 3];
        float c2 = pt0 * pw[64 + dbase]     + pt1 * pw[64 + dbase + 1]
                 + pt2 * pw[64 + dbase + 2] + pt3 * pw[64 + dbase + 3];
        #pragma unroll
        for (int o = 16; o; o >>= 1) {
            c1 += __shfl_xor_sync(0xffffffffu, c1, o);
            c2 += __shfl_xor_sync(0xffffffffu, c2, o);
        }
        if (lane == 0) {
            g_s1[w] = c1 * (1.f / 6.f);
            g_s2[w] = c2 * (1.f / 6.f);
        }
    }
}

// --------------------------- pairwise output -------------------------------
__device__ __forceinline__ float tanhfast(float x) {
    float xc = fminf(fmaxf(x, -15.f), 15.f);
    float t = __expf(2.f * xc);
    return __fdividef(t - 1.f, t + 1.f);
}

__global__ void k_pair(const float* __restrict__ dis, const float* __restrict__ pw,
                       const float* __restrict__ pb, float* __restrict__ out, int N) {
    int j4 = blockIdx.x * blockDim.x + threadIdx.x;
    int i  = blockIdx.y;
    int nq = N >> 2;
    if (j4 >= nq) return;
    float c    = __ldg(&pw[128]);
    float base = g_s2[i] + __ldg(pb);
    float4 d   = reinterpret_cast<const float4*>(dis)[(long)i * nq + j4];
    float4 s1v = reinterpret_cast<const float4*>(g_s1)[j4];
    float4 r;
    r.x = tanhfast(base + s1v.x + d.x * c);
    r.y = tanhfast(base + s1v.y + d.y * c);
    r.z = tanhfast(base + s1v.z + d.z * c);
    r.w = tanhfast(base + s1v.w + d.w * c);
    reinterpret_cast<float4*>(out)[(long)i * nq + j4] = r;
}

// ------------------------------- launcher -----------------------------------
extern "C" void kernel_launch(void* const* d_in, const int* in_sizes, int n_in,
                              void* d_out, int out_size) {
    const float* nfeats = (const float*)d_in[0];
    const float* dis    = (const float*)d_in[1];
    const int*   src    = (const int*)d_in[2];
    const int*   dst    = (const int*)d_in[3];
    const float* pw     = (const float*)d_in[20];
    const float* pb     = (const float*)d_in[21];

    const int IN = 131;
    int N = in_sizes[0] / IN;     // 5000
    int E = in_sizes[2];          // 160000
    int nchunk = (E + CSZ - 1) / CSZ;

    // CSR build (deterministic, order = edge index per dst)
    k_hist<<<nchunk, 256>>>(dst, E, N);
    k_cscan<<<(N * 32 + 255) / 256, 256>>>(N, nchunk);
    k_scan<<<1, 1024>>>(N);
    k_scatter<<<nchunk, 256>>>(src, dst, E, N);

    dim3 gg(HD / 64, (N + 127) / 128);
    int nwb = (N * 32 + 255) / 256;
    for (int l = 0; l < 4; ++l) {
        const float* W  = (const float*)d_in[4 + 4 * l];
        const float* al = (const float*)d_in[5 + 4 * l];
        const float* ar = (const float*)d_in[6 + 4 * l];
        const float* b  = (const float*)d_in[7 + 4 * l];
        int K = (l == 0) ? IN : HD;
        k_gemm<<<gg, 256>>>(l == 0 ? nfeats : nullptr, W, N, K);
        k_attn<<<nwb, 256>>>(al, ar, N);
        if (l < 3) k_agg<false><<<nwb, 256>>>(b, nullptr, N);
        else       k_agg<true><<<nwb, 256>>>(b, pw, N);
    }

    int nq = N / 4;
    dim3 gp((nq + 255) / 256, N);
    k_pair<<<gp, 256>>>(dis, pw, pb, (float*)d_out, N);
}

// round 3
// speedup vs baseline: 1.0446x; 1.0446x over previous
#include <cuda_runtime.h>
#include <cuda_bf16.h>
#include <cstdint>

// ---------------------------------------------------------------------------
// GAT (4 layers) + pairwise tanh for GB300 (sm_103a harness, compute_103 PTX).
// tcgen05 is not available at this PTX target -> use mma.sync bf16 (HMMA).
//   CSR build (deterministic) -> per layer: bf16-split HMMA GEMM ->
//   attention dots -> warp-per-node edge softmax aggregation (emits bf16
//   hi/lo operands for the next layer's GEMM) -> pairwise tanh.
// GEMM does C = Ah*Bh + Ah*Bl + Al*Bh  (fp32 accum) == extended K of 1152.
// ---------------------------------------------------------------------------

constexpr int HD  = 384;        // H*D
constexpr int NH  = 6;          // heads
constexpr int NQ  = HD / 4;     // float4 per feature row
constexpr int NMAXI = 5120;     // max nodes (actual 5000), mult of 128
constexpr int EMAXI = 163840;
constexpr int CSZ   = 320;      // edges per sort chunk
constexpr int NCH   = 512;

// ------------------------- device scratch ----------------------------------
__device__ __align__(16) float g_f[NMAXI * HD];            // fp32 GEMM out
__device__ __align__(16) __nv_bfloat16 g_Ah[NMAXI * HD];   // A hi (layer input)
__device__ __align__(16) __nv_bfloat16 g_Al[NMAXI * HD];   // A lo
__device__ __align__(16) __nv_bfloat16 g_Bh[HD * HD];      // W^T hi [n][k]
__device__ __align__(16) __nv_bfloat16 g_Bl[HD * HD];      // W^T lo
__device__ float g_el[NMAXI * NH];
__device__ float g_er[NMAXI * NH];
__device__ int   g_hist[NCH * NMAXI];
__device__ int   g_base[NMAXI];
__device__ int   g_deg[NMAXI];
__device__ int   g_csr[EMAXI];
__device__ __align__(16) float g_s1[NMAXI];
__device__ __align__(16) float g_s2[NMAXI];

// --------------------------- helpers ----------------------------------------
__device__ __forceinline__ uint32_t smem_u32(const void* p) {
    uint32_t a;
    asm("{ .reg .u64 t; cvta.to.shared.u64 t, %1; cvt.u32.u64 %0, t; }"
        : "=r"(a) : "l"(p));
    return a;
}
__device__ __forceinline__ void cpa16(uint32_t s, const void* g) {
    asm volatile("cp.async.ca.shared.global [%0], [%1], 16;"
                 :: "r"(s), "l"(g) : "memory");
}
__device__ __forceinline__ void cpa_commit() {
    asm volatile("cp.async.commit_group;" ::: "memory");
}
__device__ __forceinline__ void cpa_wait0() {
    asm volatile("cp.async.wait_group 0;" ::: "memory");
}
__device__ __forceinline__ void mma_bf16(float* d, const uint32_t* a,
                                         const uint32_t* b) {
    asm volatile(
        "mma.sync.aligned.m16n8k16.row.col.f32.bf16.bf16.f32 "
        "{%0,%1,%2,%3}, {%4,%5,%6,%7}, {%8,%9}, {%0,%1,%2,%3};"
        : "+f"(d[0]), "+f"(d[1]), "+f"(d[2]), "+f"(d[3])
        : "r"(a[0]), "r"(a[1]), "r"(a[2]), "r"(a[3]), "r"(b[0]), "r"(b[1]));
}

// bf16 split helpers
__device__ __forceinline__ void split1(float v, __nv_bfloat16& h, __nv_bfloat16& l) {
    h = __float2bfloat16(v);
    l = __float2bfloat16(v - __bfloat162float(h));
}
__device__ __forceinline__ void split_store4(uint2* oh, uint2* ol, size_t idx, float4 v) {
    __nv_bfloat16 h0, h1, h2, h3, l0, l1, l2, l3;
    split1(v.x, h0, l0); split1(v.y, h1, l1);
    split1(v.z, h2, l2); split1(v.w, h3, l3);
    uint2 hv, lv;
    hv.x = ((uint32_t)__bfloat16_as_ushort(h1) << 16) | __bfloat16_as_ushort(h0);
    hv.y = ((uint32_t)__bfloat16_as_ushort(h3) << 16) | __bfloat16_as_ushort(h2);
    lv.x = ((uint32_t)__bfloat16_as_ushort(l1) << 16) | __bfloat16_as_ushort(l0);
    lv.y = ((uint32_t)__bfloat16_as_ushort(l3) << 16) | __bfloat16_as_ushort(l2);
    oh[idx] = hv; ol[idx] = lv;
}

// ----------------------------- CSR build -----------------------------------
__global__ void k_hist(const int* __restrict__ dst, int E, int N) {
    int c = blockIdx.x;
    int* row = g_hist + c * N;
    for (int i = threadIdx.x; i < N; i += blockDim.x) row[i] = 0;
    __syncthreads();
    int e = c * CSZ + threadIdx.x;
    if (threadIdx.x < CSZ && e < E) atomicAdd(&row[dst[e]], 1);
}

__global__ void k_cscan(int N, int nchunk) {
    int w = blockIdx.x * blockDim.x + threadIdx.x;
    if (w >= N) return;
    int run = 0;
    for (int c = 0; c < nchunk; ++c) {
        int v = g_hist[c * N + w];
        g_hist[c * N + w] = run;
        run += v;
    }
    g_deg[w] = run;
}

__global__ void k_scan(int N) {
    __shared__ int wsum[32];
    int tid = threadIdx.x;
    int CH = (N + 1023) >> 10;
    int start = tid * CH;
    int loc[8];
    int sum = 0;
    #pragma unroll
    for (int i = 0; i < 8; ++i) {
        if (i < CH) {
            int idx = start + i;
            int v = (idx < N) ? g_deg[idx] : 0;
            loc[i] = sum; sum += v;
        }
    }
    int lane = tid & 31, wid = tid >> 5;
    int s = sum;
    #pragma unroll
    for (int o = 1; o < 32; o <<= 1) {
        int t = __shfl_up_sync(0xffffffffu, s, o);
        if (lane >= o) s += t;
    }
    if (lane == 31) wsum[wid] = s;
    __syncthreads();
    if (wid == 0) {
        int v = wsum[lane];
        #pragma unroll
        for (int o = 1; o < 32; o <<= 1) {
            int t = __shfl_up_sync(0xffffffffu, v, o);
            if (lane >= o) v += t;
        }
        wsum[lane] = v;
    }
    __syncthreads();
    int tbase = s - sum + (wid > 0 ? wsum[wid - 1] : 0);
    #pragma unroll
    for (int i = 0; i < 8; ++i) {
        if (i < CH) {
            int idx = start + i;
            if (idx < N) g_base[idx] = tbase + loc[i];
        }
    }
}

// parallel deterministic scatter: rank = # earlier same-dst edges in chunk
__global__ void k_scatter(const int* __restrict__ src, const int* __restrict__ dst,
                          int E, int N) {
    __shared__ int sd[CSZ];
    int c = blockIdx.x, i = threadIdx.x;
    int e = c * CSZ + i;
    int d = -1, s = 0;
    if (e < E) { d = dst[e]; s = src[e]; }
    sd[i] = d;
    __syncthreads();
    if (d >= 0) {
        int rank = 0;
        for (int j = 0; j < i; ++j) rank += (sd[j] == d);
        g_csr[g_base[d] + g_hist[c * N + d] + rank] = s;
    }
}

// --------------------------- conversions -----------------------------------
__global__ void k_convA(const float* __restrict__ src, int M, int K, int Mpad) {
    int idx = blockIdx.x * blockDim.x + threadIdx.x;
    if (idx >= Mpad * HD) return;
    int m = idx / HD, k = idx - m * HD;
    float v = (m < M && k < K) ? src[(size_t)m * K + k] : 0.f;
    __nv_bfloat16 h, l;
    split1(v, h, l);
    g_Ah[idx] = h; g_Al[idx] = l;
}

__global__ void k_convB(const float* __restrict__ W, int K) {
    int idx = blockIdx.x * blockDim.x + threadIdx.x;
    if (idx >= HD * HD) return;
    int k = idx / HD, n = idx - k * HD;
    float v = (k < K) ? W[(size_t)k * HD + n] : 0.f;
    __nv_bfloat16 h, l;
    split1(v, h, l);
    g_Bh[(size_t)n * HD + k] = h;
    g_Bl[(size_t)n * HD + k] = l;
}

// --------------------- mma.sync bf16-split GEMM ----------------------------
// block 128x128, 8 warps of 32x64; smem tiles 128 rows x 64 bf16, row stride
// 144B (conflict-free direct 32b fragment loads). 18 K-chunks of 64 cover the
// extended K = [Ah|Ah|Al] x [Bh|Bl|Bh].
constexpr int TILE_B   = 18432;                 // 128 * 144
constexpr int SM_BOFF  = 2 * TILE_B;            // B tiles after A tiles
constexpr int SM_TOTAL = 4 * TILE_B;            // 73728

__device__ __forceinline__ void load_chunk(uint32_t sb, int buf, int m0, int n0,
                                           int cc, int tid) {
    int sp = cc / 6;                 // 0: Ah*Bh  1: Ah*Bl  2: Al*Bh
    int ko = (cc - sp * 6) * 64;
    const ushort* Ag = (const ushort*)(sp == 2 ? g_Al : g_Ah) + (size_t)m0 * HD + ko;
    const ushort* Bg = (const ushort*)(sp == 1 ? g_Bl : g_Bh) + (size_t)n0 * HD + ko;
    uint32_t sa = sb + buf * TILE_B;
    uint32_t sbb = sb + SM_BOFF + buf * TILE_B;
    #pragma unroll
    for (int t = 0; t < 4; ++t) {
        int task = t * 256 + tid;        // 0..1023
        int r = task >> 3, q = task & 7;
        cpa16(sa  + r * 144 + q * 16, Ag + (size_t)r * HD + q * 8);
        cpa16(sbb + r * 144 + q * 16, Bg + (size_t)r * HD + q * 8);
    }
}

__global__ __launch_bounds__(256, 1) void k_mma(int M) {
    extern __shared__ char smem[];
    uint32_t sb = smem_u32(smem);
    int tid = threadIdx.x, lane = tid & 31, wid = tid >> 5;
    int warp_m = wid & 3, warp_n = wid >> 2;
    int g = lane >> 2, tig = lane & 3;
    int n0 = blockIdx.x * 128, m0 = blockIdx.y * 128;

    float acc[2][8][4];
    #pragma unroll
    for (int mt = 0; mt < 2; ++mt)
        #pragma unroll
        for (int nt = 0; nt < 8; ++nt)
            #pragma unroll
            for (int q = 0; q < 4; ++q) acc[mt][nt][q] = 0.f;

    load_chunk(sb, 0, m0, n0, 0, tid);
    cpa_commit();
    cpa_wait0();
    __syncthreads();

    const char* As = smem;
    const char* Bs = smem + SM_BOFF;
    int a_row0 = warp_m * 32 + g;        // + mt*16 (+8)
    int b_row0 = warp_n * 64 + g;        // + nt*8

    for (int cc = 0; cc < 18; ++cc) {
        int buf = cc & 1;
        if (cc + 1 < 18) {
            load_chunk(sb, buf ^ 1, m0, n0, cc + 1, tid);
            cpa_commit();
        }
        const char* A = As + buf * TILE_B;
        const char* B = Bs + buf * TILE_B;
        #pragma unroll
        for (int ks = 0; ks < 4; ++ks) {
            int kb = ks * 32 + tig * 4;          // byte offset in row
            uint32_t a[2][4], b[8][2];
            #pragma unroll
            for (int mt = 0; mt < 2; ++mt) {
                const char* base = A + (a_row0 + mt * 16) * 144 + kb;
                a[mt][0] = *(const uint32_t*)(base);
                a[mt][1] = *(const uint32_t*)(base + 8 * 144);
                a[mt][2] = *(const uint32_t*)(base + 16);
                a[mt][3] = *(const uint32_t*)(base + 8 * 144 + 16);
            }
            #pragma unroll
            for (int nt = 0; nt < 8; ++nt) {
                const char* base = B + (b_row0 + nt * 8) * 144 + kb;
                b[nt][0] = *(const uint32_t*)(base);
                b[nt][1] = *(const uint32_t*)(base + 16);
            }
            #pragma unroll
            for (int mt = 0; mt < 2; ++mt)
                #pragma unroll
                for (int nt = 0; nt < 8; ++nt)
                    mma_bf16(acc[mt][nt], a[mt], b[nt]);
        }
        if (cc + 1 < 18) cpa_wait0();
        __syncthreads();
    }

    // epilogue: write fp32 C
    #pragma unroll
    for (int mt = 0; mt < 2; ++mt) {
        int r0 = m0 + warp_m * 32 + mt * 16 + g;
        #pragma unroll
        for (int nt = 0; nt < 8; ++nt) {
            int col = n0 + warp_n * 64 + nt * 8 + tig * 2;
            if (r0 < M) {
                float2 v = {acc[mt][nt][0], acc[mt][nt][1]};
                *(float2*)(g_f + (size_t)r0 * HD + col) = v;
            }
            if (r0 + 8 < M) {
                float2 v = {acc[mt][nt][2], acc[mt][nt][3]};
                *(float2*)(g_f + (size_t)(r0 + 8) * HD + col) = v;
            }
        }
    }
}

// ----------------------- per-node attention dots ---------------------------
__global__ void k_attn(const float* __restrict__ al, const float* __restrict__ ar,
                       int N) {
    int w    = (blockIdx.x * blockDim.x + threadIdx.x) >> 5;
    int lane = threadIdx.x & 31;
    if (w >= N) return;
    const float* fr = g_f + (size_t)w * HD;
    #pragma unroll
    for (int h = 0; h < NH; ++h) {
        float a = fr[h * 64 + lane];
        float b = fr[h * 64 + 32 + lane];
        float sl = a * al[h * 64 + lane] + b * al[h * 64 + 32 + lane];
        float sr = a * ar[h * 64 + lane] + b * ar[h * 64 + 32 + lane];
        #pragma unroll
        for (int o = 16; o; o >>= 1) {
            sl += __shfl_xor_sync(0xffffffffu, sl, o);
            sr += __shfl_xor_sync(0xffffffffu, sr, o);
        }
        if (lane == 0) { g_el[w * NH + h] = sl; g_er[w * NH + h] = sr; }
    }
}

// ------------------- edge softmax + aggregation (warp/node) ----------------
template <bool FINAL>
__global__ void k_agg(const float* __restrict__ bias, const float* __restrict__ pw,
                      int N) {
    int w    = (blockIdx.x * blockDim.x + threadIdx.x) >> 5;
    int lane = threadIdx.x & 31;
    if (w >= N) return;
    float er_l = (lane < NH) ? g_er[w * NH + lane] : 0.f;
    int b0 = g_base[w], dg = g_deg[w];
    float4 a0 = {0.f, 0.f, 0.f, 0.f}, a1 = a0, a2 = a0;
    float den_l = 0.f;
    int h0 = lane >> 4;
    const float4* f4 = reinterpret_cast<const float4*>(g_f);

    for (int p = 0; p < dg; ++p) {
        int s = g_csr[b0 + p];
        float w_l = 0.f;
        if (lane < NH) {
            float e = g_el[s * NH + lane] + er_l;
            e = e > 0.f ? e : 0.2f * e;
            w_l = __expf(e);
            den_l += w_l;
        }
        float w0 = __shfl_sync(0xffffffffu, w_l, h0);
        float w1 = __shfl_sync(0xffffffffu, w_l, h0 + 2);
        float w2 = __shfl_sync(0xffffffffu, w_l, h0 + 4);
        const float4* fr = f4 + (size_t)s * NQ;
        float4 v0 = fr[lane], v1 = fr[lane + 32], v2 = fr[lane + 64];
        a0.x = fmaf(w0, v0.x, a0.x); a0.y = fmaf(w0, v0.y, a0.y);
        a0.z = fmaf(w0, v0.z, a0.z); a0.w = fmaf(w0, v0.w, a0.w);
        a1.x = fmaf(w1, v1.x, a1.x); a1.y = fmaf(w1, v1.y, a1.y);
        a1.z = fmaf(w1, v1.z, a1.z); a1.w = fmaf(w1, v1.w, a1.w);
        a2.x = fmaf(w2, v2.x, a2.x); a2.y = fmaf(w2, v2.y, a2.y);
        a2.z = fmaf(w2, v2.z, a2.z); a2.w = fmaf(w2, v2.w, a2.w);
    }

    float d0 = __shfl_sync(0xffffffffu, den_l, h0);
    float d1 = __shfl_sync(0xffffffffu, den_l, h0 + 2);
    float d2 = __shfl_sync(0xffffffffu, den_l, h0 + 4);
    float i0 = (dg > 0) ? 1.f / d0 : 0.f;
    float i1 = (dg > 0) ? 1.f / d1 : 0.f;
    float i2 = (dg > 0) ? 1.f / d2 : 0.f;
    const float4* b4 = reinterpret_cast<const float4*>(bias);
    float4 bv0 = b4[lane], bv1 = b4[lane + 32], bv2 = b4[lane + 64];
    float4 r0, r1, r2;
    r0.x = a0.x * i0 + bv0.x; r0.y = a0.y * i0 + bv0.y;
    r0.z = a0.z * i0 + bv0.z; r0.w = a0.w * i0 + bv0.w;
    r1.x = a1.x * i1 + bv1.x; r1.y = a1.y * i1 + bv1.y;
    r1.z = a1.z * i1 + bv1.z; r1.w = a1.w * i1 + bv1.w;
    r2.x = a2.x * i2 + bv2.x; r2.y = a2.y * i2 + bv2.y;
    r2.z = a2.z * i2 + bv2.z; r2.w = a2.w * i2 + bv2.w;

    if (!FINAL) {
        r0.x = r0.x > 0.f ? r0.x : expm1f(r0.x);
        r0.y = r0.y > 0.f ? r0.y : expm1f(r0.y);
        r0.z = r0.z > 0.f ? r0.z : expm1f(r0.z);
        r0.w = r0.w > 0.f ? r0.w : expm1f(r0.w);
        r1.x = r1.x > 0.f ? r1.x : expm1f(r1.x);
        r1.y = r1.y > 0.f ? r1.y : expm1f(r1.y);
        r1.z = r1.z > 0.f ? r1.z : expm1f(r1.z);
        r1.w = r1.w > 0.f ? r1.w : expm1f(r1.w);
        r2.x = r2.x > 0.f ? r2.x : expm1f(r2.x);
        r2.y = r2.y > 0.f ? r2.y : expm1f(r2.y);
        r2.z = r2.z > 0.f ? r2.z : expm1f(r2.z);
        r2.w = r2.w > 0.f ? r2.w : expm1f(r2.w);
        uint2* oh = reinterpret_cast<uint2*>(g_Ah);
        uint2* ol = reinterpret_cast<uint2*>(g_Al);
        size_t rb = (size_t)w * 96;
        split_store4(oh, ol, rb + lane,      r0);
        split_store4(oh, ol, rb + lane + 32, r1);
        split_store4(oh, ol, rb + lane + 64, r2);
    } else {
        float pt0 = r0.x + r1.x + r2.x;
        float pt1 = r0.y + r1.y + r2.y;
        float pt2 = r0.z + r1.z + r2.z;
        float pt3 = r0.w + r1.w + r2.w;
        int dbase = (4 * lane) & 63;
        float c1 = pt0 * pw[dbase]     + pt1 * pw[dbase + 1]
                 + pt2 * pw[dbase + 2] + pt3 * pw[dbase + 3];
        float c2 = pt0 * pw[64 + dbase]     + pt1 * pw[64 + dbase + 1]
                 + pt2 * pw[64 + dbase + 2] + pt3 * pw[64 + dbase + 3];
        #pragma unroll
        for (int o = 16; o; o >>= 1) {
            c1 += __shfl_xor_sync(0xffffffffu, c1, o);
            c2 += __shfl_xor_sync(0xffffffffu, c2, o);
        }
        if (lane == 0) {
            g_s1[w] = c1 * (1.f / 6.f);
            g_s2[w] = c2 * (1.f / 6.f);
        }
    }
}

// --------------------------- pairwise output -------------------------------
__device__ __forceinline__ float tanhfast(float x) {
    float xc = fminf(fmaxf(x, -15.f), 15.f);
    float t = __expf(2.f * xc);
    return __fdividef(t - 1.f, t + 1.f);
}

__global__ void k_pair(const float* __restrict__ dis, const float* __restrict__ pw,
                       const float* __restrict__ pb, float* __restrict__ out, int N) {
    int j4 = blockIdx.x * blockDim.x + threadIdx.x;
    int i  = blockIdx.y;
    int nq = N >> 2;
    if (j4 >= nq) return;
    float c    = __ldg(&pw[128]);
    float base = g_s2[i] + __ldg(pb);
    float4 d   = reinterpret_cast<const float4*>(dis)[(size_t)i * nq + j4];
    float4 s1v = reinterpret_cast<const float4*>(g_s1)[j4];
    float4 r;
    r.x = tanhfast(base + s1v.x + d.x * c);
    r.y = tanhfast(base + s1v.y + d.y * c);
    r.z = tanhfast(base + s1v.z + d.z * c);
    r.w = tanhfast(base + s1v.w + d.w * c);
    reinterpret_cast<float4*>(out)[(size_t)i * nq + j4] = r;
}

// ------------------------------- launcher -----------------------------------
extern "C" void kernel_launch(void* const* d_in, const int* in_sizes, int n_in,
                              void* d_out, int out_size) {
    const float* nfeats = (const float*)d_in[0];
    const float* dis    = (const float*)d_in[1];
    const int*   src    = (const int*)d_in[2];
    const int*   dst    = (const int*)d_in[3];
    const float* pw     = (const float*)d_in[20];
    const float* pb     = (const float*)d_in[21];

    const int IN = 131;
    int N = in_sizes[0] / IN;             // 5000
    int E = in_sizes[2];                  // 160000
    int nchunk = (E + CSZ - 1) / CSZ;
    int Mpad = ((N + 127) / 128) * 128;   // 5120

    cudaFuncSetAttribute(k_mma, cudaFuncAttributeMaxDynamicSharedMemorySize,
                         SM_TOTAL);

    // CSR build
    k_hist<<<nchunk, 320>>>(dst, E, N);
    k_cscan<<<(N + 255) / 256, 256>>>(N, nchunk);
    k_scan<<<1, 1024>>>(N);
    k_scatter<<<nchunk, CSZ>>>(src, dst, E, N);

    // layer-0 input conversion (zero-padded to Mpad x 384)
    k_convA<<<(Mpad * HD + 255) / 256, 256>>>(nfeats, N, IN, Mpad);

    dim3 gg(HD / 128, Mpad / 128);        // (3, 40)
    int nwb = (N * 32 + 255) / 256;
    for (int l = 0; l < 4; ++l) {
        const float* W  = (const float*)d_in[4 + 4 * l];
        const float* al = (const float*)d_in[5 + 4 * l];
        const float* ar = (const float*)d_in[6 + 4 * l];
        const float* b  = (const float*)d_in[7 + 4 * l];
        int K = (l == 0) ? IN : HD;
        k_convB<<<(HD * HD + 255) / 256, 256>>>(W, K);
        k_mma<<<gg, 256, SM_TOTAL>>>(N);
        k_attn<<<nwb, 256>>>(al, ar, N);
        if (l < 3) k_agg<false><<<nwb, 256>>>(b, nullptr, N);
        else       k_agg<true><<<nwb, 256>>>(b, pw, N);
    }

    int nq = N / 4;
    dim3 gp((nq + 255) / 256, N);
    k_pair<<<gp, 256>>>(dis, pw, pb, (float*)d_out, N);
}